// round 1
// baseline (speedup 1.0000x reference)
#include <cuda_runtime.h>

#define NIMG 2
#define CC   10
#define HH   30
#define WW   30
#define DD   11
#define PADR 4
#define LL   100

__global__ __launch_bounds__(128) void pve_kernel(
    const float* __restrict__ x,      // [2,10,30,30] one-hot
    const float* __restrict__ w_in,   // [33,11]
    const float* __restrict__ w_out,  // [11,11]
    const float* __restrict__ w_ff1,  // [1,11]
    const float* __restrict__ w_ff2,  // [11,1]
    const float* __restrict__ ln1_g,  // [11]
    const float* __restrict__ ln2_g,  // [11]
    float* __restrict__ out)          // [1800,10,100]
{
    __shared__ int   wcls[81];
    __shared__ int   hist[11];
    __shared__ float ao[11];
    __shared__ float svec[11];
    __shared__ float padvec[10];

    const int b   = blockIdx.x;
    const int n   = b / (HH * WW);
    const int rem = b % (HH * WW);
    const int pi  = rem / WW, pj = rem % WW;
    const int tid = threadIdx.x;

    if (tid < 11) hist[tid] = 0;
    __syncthreads();

    // Decode window classes from one-hot x; OOB -> class 10 (padding indicator).
    if (tid < 81) {
        int mh = tid / 9, mw = tid % 9;
        int si = pi + mh - PADR, sj = pj + mw - PADR;
        int cls = 10;
        if (si >= 0 && si < HH && sj >= 0 && sj < WW) {
            const float* px = x + ((long)n * CC * HH + si) * WW + sj;
            #pragma unroll
            for (int c = 0; c < CC; c++)
                if (px[c * HH * WW] > 0.5f) cls = c;
        }
        wcls[tid] = cls;
        atomicAdd(&hist[cls], 1);
    }
    __syncthreads();

    const bool haspad = (hist[10] > 0);

    // Attention output for the single padding-class query (per-dim heads).
    if (haspad && tid < DD) {
        const int d = tid;
        float q10 = w_in[d * DD + 10];
        float num = 0.f, den = 0.f;
        #pragma unroll
        for (int c = 0; c < DD; c++) {
            float k = w_in[(DD + d) * DD + c];
            float v = w_in[(2 * DD + d) * DD + c];
            float e = __expf(q10 * k) * (float)hist[c];
            den += e;
            num += e * v;
        }
        ao[d] = num / den;
    }
    __syncthreads();

    // seq + ao @ w_out^T   (seq = e_10)
    if (haspad && tid < DD) {
        const int dp = tid;
        float s = (dp == 10) ? 1.0f : 0.0f;
        #pragma unroll
        for (int d = 0; d < DD; d++) s += ao[d] * w_out[dp * DD + d];
        svec[dp] = s;
    }
    __syncthreads();

    // LN1 -> FF -> LN2 -> softmax(first 10), single thread (tiny, 11-dim).
    if (haspad && tid == 0) {
        float m = 0.f;
        #pragma unroll
        for (int d = 0; d < DD; d++) m += svec[d];
        m *= (1.0f / 11.0f);
        float var = 0.f;
        #pragma unroll
        for (int d = 0; d < DD; d++) { float t = svec[d] - m; var += t * t; }
        var *= (1.0f / 11.0f);
        float inv = rsqrtf(var + 1e-5f);

        float h1[DD];
        float t = 0.f;
        #pragma unroll
        for (int d = 0; d < DD; d++) {
            h1[d] = (svec[d] - m) * inv * ln1_g[d];
            t += h1[d] * w_ff1[d];
        }
        t = fmaxf(t, 0.f);

        float h2[DD];
        float m2 = 0.f;
        #pragma unroll
        for (int d = 0; d < DD; d++) { h2[d] = h1[d] + t * w_ff2[d]; m2 += h2[d]; }
        m2 *= (1.0f / 11.0f);
        float var2 = 0.f;
        #pragma unroll
        for (int d = 0; d < DD; d++) { float u = h2[d] - m2; var2 += u * u; }
        var2 *= (1.0f / 11.0f);
        float inv2 = rsqrtf(var2 + 1e-5f);

        float hh[DD];
        #pragma unroll
        for (int d = 0; d < DD; d++) hh[d] = (h2[d] - m2) * inv2 * ln2_g[d];

        float mx = -1e30f;
        #pragma unroll
        for (int c = 0; c < CC; c++) mx = fmaxf(mx, hh[c]);
        float ex[CC], se = 0.f;
        #pragma unroll
        for (int c = 0; c < CC; c++) { ex[c] = __expf(hh[c] - mx); se += ex[c]; }
        float rinv = 1.0f / se;
        #pragma unroll
        for (int c = 0; c < CC; c++) padvec[c] = ex[c] * rinv;
    }
    __syncthreads();

    // Scatter 1000 floats per pixel as 250 float4 (coalesced).
    float4* o4 = reinterpret_cast<float4*>(out + (long)b * (CC * LL));
    for (int q = tid; q < 250; q += 128) {
        int base = q * 4;
        float4 r;
        float* rp = &r.x;
        #pragma unroll
        for (int e = 0; e < 4; e++) {
            int idx = base + e;
            int c = idx / 100;
            int l = idx % 100;
            int mh = l / 10, mw = l % 10;
            float v = 0.f;
            if (mh < 9 && mw < 9) {
                int cls = wcls[mh * 9 + mw];
                v = (cls == 10) ? padvec[c] : (cls == c ? 1.0f : 0.0f);
            }
            rp[e] = v;
        }
        o4[q] = r;
    }
}

extern "C" void kernel_launch(void* const* d_in, const int* in_sizes, int n_in,
                              void* d_out, int out_size) {
    const float* x     = (const float*)d_in[0];
    const float* w_in  = (const float*)d_in[1];
    const float* w_out = (const float*)d_in[2];
    const float* w_ff1 = (const float*)d_in[3];
    const float* w_ff2 = (const float*)d_in[4];
    const float* ln1_g = (const float*)d_in[5];
    const float* ln2_g = (const float*)d_in[6];
    pve_kernel<<<NIMG * HH * WW, 128>>>(x, w_in, w_out, w_ff1, w_ff2,
                                        ln1_g, ln2_g, (float*)d_out);
}

// round 2
// speedup vs baseline: 1.1837x; 1.1837x over previous
#include <cuda_runtime.h>

#define NIMG 2
#define CC   10
#define HH   30
#define WW   30
#define DD   11
#define PADR 4

// Pre-decoded class per pixel (0..9). Scratch: __device__ global (no alloc).
__device__ unsigned char g_clsmap[NIMG * HH * WW];

__global__ __launch_bounds__(128) void decode_kernel(const float* __restrict__ x) {
    int t = blockIdx.x * 128 + threadIdx.x;
    if (t >= NIMG * HH * WW) return;
    int n = t / (HH * WW);
    int p = t % (HH * WW);
    const float* px = x + (long)n * CC * HH * WW + p;
    int cls = 0;
    #pragma unroll
    for (int c = 0; c < CC; c++)
        if (px[c * HH * WW] > 0.5f) cls = c;
    g_clsmap[t] = (unsigned char)cls;
}

__global__ __launch_bounds__(128) void pve_kernel(
    const float* __restrict__ w_in,   // [33,11]
    const float* __restrict__ w_out,  // [11,11]
    const float* __restrict__ w_ff1,  // [1,11]
    const float* __restrict__ w_ff2,  // [11,1]
    const float* __restrict__ ln1_g,  // [11]
    const float* __restrict__ ln2_g,  // [11]
    float* __restrict__ out)          // [1800,10,100]
{
    __shared__ union { unsigned char b[104]; unsigned int w[26]; } lcls;
    __shared__ int   hist[11];
    __shared__ float ao[11];
    __shared__ float svec[11];
    __shared__ float padvec[10];

    const int b   = blockIdx.x;
    const int n   = b / (HH * WW);
    const int rem = b % (HH * WW);
    const int pi  = rem / WW, pj = rem % WW;
    const int tid = threadIdx.x;

    // Border blocks are the only ones whose window contains padding tokens.
    const bool haspad = (pi < PADR) | (pi > HH - 1 - PADR) |
                        (pj < PADR) | (pj > WW - 1 - PADR);

    if (haspad && tid < 11) hist[tid] = 0;
    if (haspad) __syncthreads();   // uniform branch: safe

    // Build per-l class table: l = mh*10+mw, mh,mw in [0,10); slot masked when
    // mh==9 || mw==9 (255), OOB window position -> class 10, else class map.
    if (tid < 100) {
        int mh = tid / 10, mw = tid % 10;
        unsigned char cls = 255;
        if (mh < 9 && mw < 9) {
            int si = pi + mh - PADR, sj = pj + mw - PADR;
            cls = 10;
            if (si >= 0 && si < HH && sj >= 0 && sj < WW)
                cls = g_clsmap[(n * HH + si) * WW + sj];
            if (haspad) atomicAdd(&hist[cls], 1);
        }
        lcls.b[tid] = cls;
    }
    __syncthreads();

    if (haspad) {
        // Whole padding pipeline lives in warp 0 (tiny, 11-dim).
        if (tid < 32) {
            if (tid < DD) {
                const int d = tid;
                float q10 = w_in[d * DD + 10];
                float num = 0.f, den = 0.f;
                #pragma unroll
                for (int c = 0; c < DD; c++) {
                    float k = w_in[(DD + d) * DD + c];
                    float v = w_in[(2 * DD + d) * DD + c];
                    float e = __expf(q10 * k) * (float)hist[c];
                    den += e;
                    num += e * v;
                }
                ao[d] = num / den;
            }
            __syncwarp();
            if (tid < DD) {
                const int dp = tid;
                float s = (dp == 10) ? 1.0f : 0.0f;
                #pragma unroll
                for (int d = 0; d < DD; d++) s += ao[d] * w_out[dp * DD + d];
                svec[dp] = s;
            }
            __syncwarp();
            if (tid == 0) {
                float m = 0.f;
                #pragma unroll
                for (int d = 0; d < DD; d++) m += svec[d];
                m *= (1.0f / 11.0f);
                float var = 0.f;
                #pragma unroll
                for (int d = 0; d < DD; d++) { float t = svec[d] - m; var += t * t; }
                var *= (1.0f / 11.0f);
                float inv = rsqrtf(var + 1e-5f);

                float h1[DD];
                float t = 0.f;
                #pragma unroll
                for (int d = 0; d < DD; d++) {
                    h1[d] = (svec[d] - m) * inv * ln1_g[d];
                    t += h1[d] * w_ff1[d];
                }
                t = fmaxf(t, 0.f);

                float h2[DD];
                float m2 = 0.f;
                #pragma unroll
                for (int d = 0; d < DD; d++) { h2[d] = h1[d] + t * w_ff2[d]; m2 += h2[d]; }
                m2 *= (1.0f / 11.0f);
                float var2 = 0.f;
                #pragma unroll
                for (int d = 0; d < DD; d++) { float u = h2[d] - m2; var2 += u * u; }
                var2 *= (1.0f / 11.0f);
                float inv2 = rsqrtf(var2 + 1e-5f);

                float hh[DD];
                #pragma unroll
                for (int d = 0; d < DD; d++) hh[d] = (h2[d] - m2) * inv2 * ln2_g[d];

                float mx = -1e30f;
                #pragma unroll
                for (int c = 0; c < CC; c++) mx = fmaxf(mx, hh[c]);
                float ex[CC], se = 0.f;
                #pragma unroll
                for (int c = 0; c < CC; c++) { ex[c] = __expf(hh[c] - mx); se += ex[c]; }
                float rinv = 1.0f / se;
                #pragma unroll
                for (int c = 0; c < CC; c++) padvec[c] = ex[c] * rinv;
            }
        }
        __syncthreads();
    }

    // Scatter 1000 floats as 250 float4. q = c*25 + j, word j of lcls covers
    // l = 4j..4j+3. Per element: shift/mask + 2 compares, no div/mod.
    float4* o4 = reinterpret_cast<float4*>(out + (long)b * 1000);
    #pragma unroll
    for (int pass = 0; pass < 2; pass++) {
        int q = tid + pass * 128;
        if (q < 250) {
            int c = q / 25;          // magic-mul, hoisted per float4
            int j = q - c * 25;
            unsigned int w = lcls.w[j];
            float pv = haspad ? padvec[c] : 0.f;
            float4 r;
            float* rp = &r.x;
            #pragma unroll
            for (int e = 0; e < 4; e++) {
                unsigned int cls = (w >> (8 * e)) & 0xFF;
                float v = 0.f;
                if (cls != 255) v = (cls == 10) ? pv : (cls == (unsigned)c ? 1.0f : 0.0f);
                rp[e] = v;
            }
            o4[q] = r;
        }
    }
}

extern "C" void kernel_launch(void* const* d_in, const int* in_sizes, int n_in,
                              void* d_out, int out_size) {
    const float* x     = (const float*)d_in[0];
    const float* w_in  = (const float*)d_in[1];
    const float* w_out = (const float*)d_in[2];
    const float* w_ff1 = (const float*)d_in[3];
    const float* w_ff2 = (const float*)d_in[4];
    const float* ln1_g = (const float*)d_in[5];
    const float* ln2_g = (const float*)d_in[6];

    decode_kernel<<<(NIMG * HH * WW + 127) / 128, 128>>>(x);
    pve_kernel<<<NIMG * HH * WW, 128>>>(w_in, w_out, w_ff1, w_ff2,
                                        ln1_g, ln2_g, (float*)d_out);
}